// round 1
// baseline (speedup 1.0000x reference)
#include <cuda_runtime.h>
#include <math.h>

#define D 512
#define NBLOCKS 1184
#define BLK 256
#define WARPS_PER_BLK (BLK / 32)
#define EPSN (1e-13f + 1e-14f)

__device__ float g_partial[NBLOCKS];

__global__ __launch_bounds__(BLK) void rowcos_kernel(const float* __restrict__ s,
                                                     const float* __restrict__ im,
                                                     int N) {
    const int lane = threadIdx.x & 31;
    const int gwarp = (blockIdx.x * BLK + threadIdx.x) >> 5;
    const int nwarps = (gridDim.x * BLK) >> 5;

    float acc = 0.0f;

    for (int row = gwarp; row < N; row += nwarps) {
        const float4* sp = reinterpret_cast<const float4*>(s + (size_t)row * D);
        const float4* ip = reinterpret_cast<const float4*>(im + (size_t)row * D);

        float dot = 0.0f, ss = 0.0f, ii = 0.0f;
        // D/4 = 128 float4 per row, 32 lanes -> 4 float4 per lane per array.
        // Independent loads (MLP=8) to hide DRAM latency.
        float4 a[4], b[4];
#pragma unroll
        for (int j = 0; j < 4; j++) {
            a[j] = sp[lane + j * 32];
            b[j] = ip[lane + j * 32];
        }
#pragma unroll
        for (int j = 0; j < 4; j++) {
            dot += a[j].x * b[j].x + a[j].y * b[j].y + a[j].z * b[j].z + a[j].w * b[j].w;
            ss  += a[j].x * a[j].x + a[j].y * a[j].y + a[j].z * a[j].z + a[j].w * a[j].w;
            ii  += b[j].x * b[j].x + b[j].y * b[j].y + b[j].z * b[j].z + b[j].w * b[j].w;
        }

        // warp tree-reduce the three sums
#pragma unroll
        for (int off = 16; off > 0; off >>= 1) {
            dot += __shfl_xor_sync(0xffffffffu, dot, off);
            ss  += __shfl_xor_sync(0xffffffffu, ss,  off);
            ii  += __shfl_xor_sync(0xffffffffu, ii,  off);
        }

        // all lanes hold the same value; accumulate once conceptually
        if (lane == 0) {
            acc -= dot / ((sqrtf(ss) + EPSN) * (sqrtf(ii) + EPSN));
        }
    }

    __shared__ float wsum[WARPS_PER_BLK];
    if (lane == 0) wsum[threadIdx.x >> 5] = acc;
    __syncthreads();

    if (threadIdx.x == 0) {
        float bsum = 0.0f;
#pragma unroll
        for (int w = 0; w < WARPS_PER_BLK; w++) bsum += wsum[w];
        g_partial[blockIdx.x] = bsum;
    }
}

__global__ __launch_bounds__(256) void finalize_kernel(float* __restrict__ out) {
    __shared__ float sm[256];
    float v = 0.0f;
    for (int i = threadIdx.x; i < NBLOCKS; i += 256) v += g_partial[i];
    sm[threadIdx.x] = v;
    __syncthreads();
    for (int s = 128; s > 0; s >>= 1) {
        if (threadIdx.x < s) sm[threadIdx.x] += sm[threadIdx.x + s];
        __syncthreads();
    }
    if (threadIdx.x == 0) out[0] = sm[0];
}

extern "C" void kernel_launch(void* const* d_in, const int* in_sizes, int n_in,
                              void* d_out, int out_size) {
    const float* s  = (const float*)d_in[0];
    const float* im = (const float*)d_in[1];
    const int N = in_sizes[0] / D;

    rowcos_kernel<<<NBLOCKS, BLK>>>(s, im, N);
    finalize_kernel<<<1, 256>>>((float*)d_out);
}

// round 2
// speedup vs baseline: 1.0276x; 1.0276x over previous
#include <cuda_runtime.h>
#include <math.h>

#define D 512
#define NBLOCKS 1184
#define BLK 256
#define WARPS_PER_BLK (BLK / 32)
#define EPSN (1e-13f + 1e-14f)

__device__ float g_partial[NBLOCKS];

__global__ __launch_bounds__(BLK) void rowcos_kernel(const float* __restrict__ s,
                                                     const float* __restrict__ im,
                                                     int N) {
    const int lane = threadIdx.x & 31;
    const int gwarp = (blockIdx.x * BLK + threadIdx.x) >> 5;
    const int nwarps = (gridDim.x * BLK) >> 5;

    float acc = 0.0f;

    for (int row = gwarp; row < N; row += nwarps) {
        const float4* sp = reinterpret_cast<const float4*>(s + (size_t)row * D);
        const float4* ip = reinterpret_cast<const float4*>(im + (size_t)row * D);

        float dot = 0.0f, ss = 0.0f, ii = 0.0f;
        // D/4 = 128 float4 per row, 32 lanes -> 4 float4 per lane per array.
        // Independent loads (MLP=8) to hide DRAM latency.
        float4 a[4], b[4];
#pragma unroll
        for (int j = 0; j < 4; j++) {
            a[j] = sp[lane + j * 32];
            b[j] = ip[lane + j * 32];
        }
#pragma unroll
        for (int j = 0; j < 4; j++) {
            dot += a[j].x * b[j].x + a[j].y * b[j].y + a[j].z * b[j].z + a[j].w * b[j].w;
            ss  += a[j].x * a[j].x + a[j].y * a[j].y + a[j].z * a[j].z + a[j].w * a[j].w;
            ii  += b[j].x * b[j].x + b[j].y * b[j].y + b[j].z * b[j].z + b[j].w * b[j].w;
        }

        // warp tree-reduce the three sums
#pragma unroll
        for (int off = 16; off > 0; off >>= 1) {
            dot += __shfl_xor_sync(0xffffffffu, dot, off);
            ss  += __shfl_xor_sync(0xffffffffu, ss,  off);
            ii  += __shfl_xor_sync(0xffffffffu, ii,  off);
        }

        // all lanes hold the same value; accumulate once conceptually
        if (lane == 0) {
            acc -= dot / ((sqrtf(ss) + EPSN) * (sqrtf(ii) + EPSN));
        }
    }

    __shared__ float wsum[WARPS_PER_BLK];
    if (lane == 0) wsum[threadIdx.x >> 5] = acc;
    __syncthreads();

    if (threadIdx.x == 0) {
        float bsum = 0.0f;
#pragma unroll
        for (int w = 0; w < WARPS_PER_BLK; w++) bsum += wsum[w];
        g_partial[blockIdx.x] = bsum;
    }
}

__global__ __launch_bounds__(256) void finalize_kernel(float* __restrict__ out) {
    __shared__ float sm[256];
    float v = 0.0f;
    for (int i = threadIdx.x; i < NBLOCKS; i += 256) v += g_partial[i];
    sm[threadIdx.x] = v;
    __syncthreads();
    for (int s = 128; s > 0; s >>= 1) {
        if (threadIdx.x < s) sm[threadIdx.x] += sm[threadIdx.x + s];
        __syncthreads();
    }
    if (threadIdx.x == 0) out[0] = sm[0];
}

extern "C" void kernel_launch(void* const* d_in, const int* in_sizes, int n_in,
                              void* d_out, int out_size) {
    const float* s  = (const float*)d_in[0];
    const float* im = (const float*)d_in[1];
    const int N = in_sizes[0] / D;

    rowcos_kernel<<<NBLOCKS, BLK>>>(s, im, N);
    finalize_kernel<<<1, 256>>>((float*)d_out);
}